// round 8
// baseline (speedup 1.0000x reference)
#include <cuda_runtime.h>
#include <cuda_fp16.h>

#define BATCH 2
#define C_CH  256
#define FH    192
#define FW    192
#define PH    7
#define PW    7
#define NBIN  (PH*PW)          // 49
#define PLANE (FH*FW)          // 36864
#define SMEM_PITCH 260         // fp32 per bin-row in staging smem
#define MAXBIN 25              // bins per block (split 25/24)

// NHWC fp16 copy of the feature map: (B, H, W, C) = 37.7 MB
__device__ __half g_nhwc[BATCH * FH * FW * C_CH];

// ---------------------------------------------------------------------------
// packed f32x2 helpers (sm_103a FFMA2 — only reachable via PTX)
// ---------------------------------------------------------------------------
__device__ __forceinline__ unsigned long long pack2(float a, float b) {
    unsigned long long r;
    asm("mov.b64 %0, {%1, %2};" : "=l"(r) : "f"(a), "f"(b));
    return r;
}
__device__ __forceinline__ void ffma2(unsigned long long& acc,
                                      unsigned long long v,
                                      unsigned long long w) {
    asm("fma.rn.f32x2 %0, %1, %2, %0;" : "+l"(acc) : "l"(v), "l"(w));
}
__device__ __forceinline__ float2 unpack2(unsigned long long v) {
    float2 f;
    asm("mov.b64 {%0, %1}, %2;" : "=f"(f.x), "=f"(f.y) : "l"(v));
    return f;
}

// ---------------------------------------------------------------------------
// Kernel 1: NCHW fp32 -> NHWC fp16 transpose (unchanged this round)
// ---------------------------------------------------------------------------
__global__ __launch_bounds__(256)
void transpose_kernel(const float* __restrict__ in)
{
    __shared__ __half tile[32][66];
    int pTile = blockIdx.x * 32;
    int cTile = blockIdx.y * 64;
    int b     = blockIdx.z;
    int tx = threadIdx.x;
    int ty = threadIdx.y;

    const float* src = in + (size_t)b * C_CH * PLANE;

    #pragma unroll
    for (int j = 0; j < 8; j++) {
        int cl = ty + 8 * j;
        int c  = cTile + cl;
        tile[tx][cl] = __float2half(src[(size_t)c * PLANE + pTile + tx]);
    }
    __syncthreads();

    __half2* dst = (__half2*)(g_nhwc + (size_t)b * PLANE * C_CH);
    #pragma unroll
    for (int j = 0; j < 4; j++) {
        int pl = ty + 8 * j;
        int p  = pTile + pl;
        __half2 h = ((const __half2*)&tile[pl][0])[tx];
        dst[(size_t)p * (C_CH / 2) + (cTile / 2) + tx] = h;
    }
}

// ---------------------------------------------------------------------------
// Kernel 2: one block handles CNT bins of one roi.
// Thread = 4 fp16 channels (uint2) x bin-subset. 2-sample pipelined loads
// (MLP 8 x 8B per thread) + packed f32x2 FMAs. Low regs -> 6 CTAs/SM.
// ---------------------------------------------------------------------------
__device__ __forceinline__ void load_taps(const uint2* __restrict__ fp,
                                          int4 off, int cg, uint2 q[4])
{
    q[0] = __ldg(fp + off.x + cg);
    q[1] = __ldg(fp + off.y + cg);
    q[2] = __ldg(fp + off.z + cg);
    q[3] = __ldg(fp + off.w + cg);
}

__device__ __forceinline__ void acc_taps(const uint2 q[4], float4 w,
                                         unsigned long long& acc0,
                                         unsigned long long& acc1)
{
    #pragma unroll
    for (int k = 0; k < 4; k++) {
        float wk = (k == 0) ? w.x : (k == 1) ? w.y : (k == 2) ? w.z : w.w;
        unsigned long long w2 = pack2(wk, wk);
        const __half2* hh = (const __half2*)&q[k];
        float2 f0 = __half22float2(hh[0]);
        float2 f1 = __half22float2(hh[1]);
        ffma2(acc0, pack2(f0.x, f0.y), w2);
        ffma2(acc1, pack2(f1.x, f1.y), w2);
    }
}

template<int S0, int CNT>
__device__ __forceinline__
void roi_body(float* sacc, int4* goff, float4* gw,
              const float* __restrict__ rois,
              const void*  __restrict__ stride_ptr,
              float* __restrict__ out)
{
    int n   = blockIdx.x;
    int tid = threadIdx.x;
    int cg  = tid & 63;        // channel group: channels 4cg..4cg+3
    int sg  = tid >> 6;        // bin subset 0..3

    const float* r = rois + n * 5;
    int b = (int)r[0];

    // ---- Phase A: geometry precompute (one thread per sample) ----
    if (tid < CNT * 4) {
        int iv = *(const int*)stride_ptr;
        float stride_f = (iv > 0 && iv < 65536) ? (float)iv
                                                : *(const float*)stride_ptr;
        float scale = 1.0f / stride_f;

        float x1 = r[1] * scale;
        float y1 = r[2] * scale;
        float x2 = r[3] * scale;
        float y2 = r[4] * scale;
        float bin_w = fmaxf(x2 - x1, 1.0f) * (1.0f / PW);
        float bin_h = fmaxf(y2 - y1, 1.0f) * (1.0f / PH);

        int s  = S0 + (tid >> 2);
        int j  = tid & 3;
        int iy = j >> 1;
        int ix = j & 1;
        int ph = s / PW;
        int pw = s - ph * PW;

        float yy = y1 + ((float)(ph * 2 + iy) + 0.5f) * 0.5f * bin_h;
        float xx = x1 + ((float)(pw * 2 + ix) + 0.5f) * 0.5f * bin_w;
        bool vy = (yy > -1.0f) && (yy < (float)FH);
        bool vx = (xx > -1.0f) && (xx < (float)FW);

        float cy = fminf(fmaxf(yy, 0.0f), (float)(FH - 1));
        float cx = fminf(fmaxf(xx, 0.0f), (float)(FW - 1));
        int y0 = min((int)floorf(cy), FH - 1);
        int x0 = min((int)floorf(cx), FW - 1);
        int y1r = min(y0 + 1, FH - 1);
        int x1r = min(x0 + 1, FW - 1);
        float fy = cy - (float)y0;
        float fx = cx - (float)x0;
        float hy = 1.0f - fy;
        float hx = 1.0f - fx;

        // fold mask AND the 1/4 mean (exact, power of two) into weights
        float m = (vy && vx) ? 0.25f : 0.0f;
        gw[tid]   = make_float4(m*hy*hx, m*hy*fx, m*fy*hx, m*fy*fx);
        goff[tid] = make_int4((y0  * FW + x0 ) * (C_CH/4),
                              (y0  * FW + x1r) * (C_CH/4),
                              (y1r * FW + x0 ) * (C_CH/4),
                              (y1r * FW + x1r) * (C_CH/4));
    }
    __syncthreads();

    // ---- Phase B: accumulate, 2-sample pipelined loads ----
    const uint2* fp = (const uint2*)(g_nhwc) + (size_t)b * PLANE * (C_CH / 4);

    for (int sl = sg; sl < CNT; sl += 4) {
        unsigned long long acc0 = 0, acc1 = 0;

        uint2 qa[4], qb[4];
        load_taps(fp, goff[sl*4+0], cg, qa);   // sample 0 in flight
        load_taps(fp, goff[sl*4+1], cg, qb);   // sample 1 in flight (MLP 8)
        acc_taps(qa, gw[sl*4+0], acc0, acc1);
        load_taps(fp, goff[sl*4+2], cg, qa);   // sample 2 in flight
        acc_taps(qb, gw[sl*4+1], acc0, acc1);
        load_taps(fp, goff[sl*4+3], cg, qb);   // sample 3 in flight
        acc_taps(qa, gw[sl*4+2], acc0, acc1);
        acc_taps(qb, gw[sl*4+3], acc0, acc1);

        float2 a0 = unpack2(acc0), a1 = unpack2(acc1);
        // STS.128, lanes cg-consecutive -> conflict-free
        *(float4*)&sacc[sl * SMEM_PITCH + 4 * cg] =
            make_float4(a0.x, a0.y, a1.x, a1.y);
    }

    __syncthreads();

    // ---- Phase C: coalesced writeout out[n][c][S0+sl] ----
    float* obase = out + (size_t)n * (C_CH * NBIN) + S0;
    for (int t = tid; t < C_CH * CNT; t += 256) {
        int c  = t / CNT;          // constexpr CNT -> magic multiply
        int sl = t - c * CNT;
        obase[c * NBIN + sl] = sacc[sl * SMEM_PITCH + c];
    }
}

__global__ __launch_bounds__(256, 6)
void roi_align_nhwc_kernel(const float* __restrict__ rois,
                           const void*  __restrict__ stride_ptr,
                           float* __restrict__ out)
{
    __shared__ float  sacc[MAXBIN * SMEM_PITCH];  // 26 KB
    __shared__ int4   goff[MAXBIN * 4];           // 1.6 KB
    __shared__ float4 gw[MAXBIN * 4];             // 1.6 KB

    if (blockIdx.y == 0)
        roi_body<0, 25>(sacc, goff, gw, rois, stride_ptr, out);
    else
        roi_body<25, 24>(sacc, goff, gw, rois, stride_ptr, out);
}

extern "C" void kernel_launch(void* const* d_in, const int* in_sizes, int n_in,
                              void* d_out, int out_size)
{
    const float* rois    = (const float*)d_in[0];
    const float* feature = (const float*)d_in[1];
    const void*  stridep = d_in[2];
    float* out = (float*)d_out;

    int N = in_sizes[0] / 5;

    dim3 tgrid(PLANE / 32, C_CH / 64, BATCH);
    dim3 tblk(32, 8);
    transpose_kernel<<<tgrid, tblk>>>(feature);

    dim3 rgrid(N, 2);
    roi_align_nhwc_kernel<<<rgrid, 256>>>(rois, stridep, out);
}

// round 9
// speedup vs baseline: 1.1147x; 1.1147x over previous
#include <cuda_runtime.h>
#include <cuda_fp16.h>

#define BATCH 2
#define C_CH  256
#define FH    192
#define FW    192
#define PH    7
#define PW    7
#define NBIN  (PH*PW)          // 49
#define PLANE (FH*FW)          // 36864
#define SMEM_PITCH 260         // fp32 per bin-row in staging smem
#define MAXBIN 25              // bins per block (split 25/24)

// NHWC fp16 copy of the feature map: (B, H, W, C) = 37.7 MB
__device__ __half g_nhwc[BATCH * FH * FW * C_CH];

// ---------------------------------------------------------------------------
// Kernel 1: NCHW fp32 -> NHWC fp16 transpose (unchanged; ~DRAM-bound)
// ---------------------------------------------------------------------------
__global__ __launch_bounds__(256)
void transpose_kernel(const float* __restrict__ in)
{
    __shared__ __half tile[32][66];
    int pTile = blockIdx.x * 32;
    int cTile = blockIdx.y * 64;
    int b     = blockIdx.z;
    int tx = threadIdx.x;
    int ty = threadIdx.y;

    const float* src = in + (size_t)b * C_CH * PLANE;

    #pragma unroll
    for (int j = 0; j < 8; j++) {
        int cl = ty + 8 * j;
        int c  = cTile + cl;
        tile[tx][cl] = __float2half(src[(size_t)c * PLANE + pTile + tx]);
    }
    __syncthreads();

    __half2* dst = (__half2*)(g_nhwc + (size_t)b * PLANE * C_CH);
    #pragma unroll
    for (int j = 0; j < 4; j++) {
        int pl = ty + 8 * j;
        int p  = pTile + pl;
        __half2 h = ((const __half2*)&tile[pl][0])[tx];
        dst[(size_t)p * (C_CH / 2) + (cTile / 2) + tx] = h;
    }
}

// ---------------------------------------------------------------------------
// Kernel 2: one block handles CNT bins of one roi.
// Lanes: cg = tid&31 -> 8 fp16 channels via uint4 LDG.128 (R7 width).
// Pipeline: 2-sample double buffer, MLP 8 (R7 schedule).
// Math: fp16 HFMA2 4-tap partial per sample, one fp16->fp32 convert+add
//       per sample into fp32 accumulators (R6 numerics).
// ---------------------------------------------------------------------------
__device__ __forceinline__ void load_taps(const uint4* __restrict__ fp,
                                          int4 off, int cg, uint4 q[4])
{
    q[0] = __ldg(fp + off.x + cg);
    q[1] = __ldg(fp + off.y + cg);
    q[2] = __ldg(fp + off.z + cg);
    q[3] = __ldg(fp + off.w + cg);
}

__device__ __forceinline__ void acc_sample(const uint4 q[4], uint4 wq,
                                           float a[8])
{
    __half2 p0 = __float2half2_rn(0.f);
    __half2 p1 = p0, p2 = p0, p3 = p0;

    #pragma unroll
    for (int k = 0; k < 4; k++) {
        unsigned int wu = (k == 0) ? wq.x : (k == 1) ? wq.y
                        : (k == 2) ? wq.z : wq.w;
        __half2 w2 = *(__half2*)&wu;
        const __half2* h = (const __half2*)&q[k];
        p0 = __hfma2(h[0], w2, p0);
        p1 = __hfma2(h[1], w2, p1);
        p2 = __hfma2(h[2], w2, p2);
        p3 = __hfma2(h[3], w2, p3);
    }

    float2 f0 = __half22float2(p0);
    float2 f1 = __half22float2(p1);
    float2 f2 = __half22float2(p2);
    float2 f3 = __half22float2(p3);
    a[0] += f0.x; a[1] += f0.y; a[2] += f1.x; a[3] += f1.y;
    a[4] += f2.x; a[5] += f2.y; a[6] += f3.x; a[7] += f3.y;
}

template<int S0, int CNT>
__device__ __forceinline__
void roi_body(float* sacc, int4* goff, uint4* gwh,
              const float* __restrict__ rois,
              const void*  __restrict__ stride_ptr,
              float* __restrict__ out)
{
    int n   = blockIdx.x;
    int tid = threadIdx.x;
    int cg  = tid & 31;        // channel group: channels 8cg..8cg+7
    int sg  = tid >> 5;        // bin subset 0..7

    const float* r = rois + n * 5;
    int b = (int)r[0];

    // ---- Phase A: geometry precompute (one thread per sample) ----
    if (tid < CNT * 4) {
        int iv = *(const int*)stride_ptr;
        float stride_f = (iv > 0 && iv < 65536) ? (float)iv
                                                : *(const float*)stride_ptr;
        float scale = 1.0f / stride_f;

        float x1 = r[1] * scale;
        float y1 = r[2] * scale;
        float x2 = r[3] * scale;
        float y2 = r[4] * scale;
        float bin_w = fmaxf(x2 - x1, 1.0f) * (1.0f / PW);
        float bin_h = fmaxf(y2 - y1, 1.0f) * (1.0f / PH);

        int s  = S0 + (tid >> 2);
        int j  = tid & 3;
        int iy = j >> 1;
        int ix = j & 1;
        int ph = s / PW;
        int pw = s - ph * PW;

        float yy = y1 + ((float)(ph * 2 + iy) + 0.5f) * 0.5f * bin_h;
        float xx = x1 + ((float)(pw * 2 + ix) + 0.5f) * 0.5f * bin_w;
        bool vy = (yy > -1.0f) && (yy < (float)FH);
        bool vx = (xx > -1.0f) && (xx < (float)FW);

        float cy = fminf(fmaxf(yy, 0.0f), (float)(FH - 1));
        float cx = fminf(fmaxf(xx, 0.0f), (float)(FW - 1));
        int y0 = min((int)floorf(cy), FH - 1);
        int x0 = min((int)floorf(cx), FW - 1);
        int y1r = min(y0 + 1, FH - 1);
        int x1r = min(x0 + 1, FW - 1);
        float fy = cy - (float)y0;
        float fx = cx - (float)x0;
        float hy = 1.0f - fy;
        float hx = 1.0f - fx;

        // fold mask and the 1/4 mean into fp16-duplicated weights
        float m = (vy && vx) ? 0.25f : 0.0f;
        __half2 w00 = __float2half2_rn(m * hy * hx);
        __half2 w01 = __float2half2_rn(m * hy * fx);
        __half2 w10 = __float2half2_rn(m * fy * hx);
        __half2 w11 = __float2half2_rn(m * fy * fx);
        uint4 wq;
        wq.x = *(unsigned int*)&w00;
        wq.y = *(unsigned int*)&w01;
        wq.z = *(unsigned int*)&w10;
        wq.w = *(unsigned int*)&w11;
        gwh[tid]  = wq;
        goff[tid] = make_int4((y0  * FW + x0 ) * (C_CH/8),
                              (y0  * FW + x1r) * (C_CH/8),
                              (y1r * FW + x0 ) * (C_CH/8),
                              (y1r * FW + x1r) * (C_CH/8));
    }
    __syncthreads();

    // ---- Phase B: accumulate, 2-sample pipelined loads (MLP 8) ----
    const uint4* fp = (const uint4*)(g_nhwc) + (size_t)b * PLANE * (C_CH / 8);

    for (int sl = sg; sl < CNT; sl += 8) {
        float a[8] = {0.f, 0.f, 0.f, 0.f, 0.f, 0.f, 0.f, 0.f};

        uint4 qa[4], qb[4];
        load_taps(fp, goff[sl*4+0], cg, qa);   // sample 0 in flight
        load_taps(fp, goff[sl*4+1], cg, qb);   // sample 1 in flight (MLP 8)
        acc_sample(qa, gwh[sl*4+0], a);
        load_taps(fp, goff[sl*4+2], cg, qa);   // sample 2 in flight
        acc_sample(qb, gwh[sl*4+1], a);
        load_taps(fp, goff[sl*4+3], cg, qb);   // sample 3 in flight
        acc_sample(qa, gwh[sl*4+2], a);
        acc_sample(qb, gwh[sl*4+3], a);

        float* sp = &sacc[sl * SMEM_PITCH + 8 * cg];
        *(float4*)(sp + 0) = make_float4(a[0], a[1], a[2], a[3]);
        *(float4*)(sp + 4) = make_float4(a[4], a[5], a[6], a[7]);
    }

    __syncthreads();

    // ---- Phase C: coalesced writeout out[n][c][S0+sl] ----
    float* obase = out + (size_t)n * (C_CH * NBIN) + S0;
    for (int t = tid; t < C_CH * CNT; t += 256) {
        int c  = t / CNT;          // constexpr CNT -> magic multiply
        int sl = t - c * CNT;
        obase[c * NBIN + sl] = sacc[sl * SMEM_PITCH + c];
    }
}

__global__ __launch_bounds__(256, 5)
void roi_align_nhwc_kernel(const float* __restrict__ rois,
                           const void*  __restrict__ stride_ptr,
                           float* __restrict__ out)
{
    __shared__ float sacc[MAXBIN * SMEM_PITCH];  // 26 KB
    __shared__ int4  goff[MAXBIN * 4];           // 1.6 KB
    __shared__ uint4 gwh[MAXBIN * 4];            // 1.6 KB

    if (blockIdx.y == 0)
        roi_body<0, 25>(sacc, goff, gwh, rois, stride_ptr, out);
    else
        roi_body<25, 24>(sacc, goff, gwh, rois, stride_ptr, out);
}

extern "C" void kernel_launch(void* const* d_in, const int* in_sizes, int n_in,
                              void* d_out, int out_size)
{
    const float* rois    = (const float*)d_in[0];
    const float* feature = (const float*)d_in[1];
    const void*  stridep = d_in[2];
    float* out = (float*)d_out;

    int N = in_sizes[0] / 5;

    dim3 tgrid(PLANE / 32, C_CH / 64, BATCH);
    dim3 tblk(32, 8);
    transpose_kernel<<<tgrid, tblk>>>(feature);

    dim3 rgrid(N, 2);
    roi_align_nhwc_kernel<<<rgrid, 256>>>(rois, stridep, out);
}

// round 12
// speedup vs baseline: 1.1211x; 1.0057x over previous
#include <cuda_runtime.h>
#include <cuda_fp16.h>

#define BATCH 2
#define C_CH  256
#define FH    192
#define FW    192
#define PH    7
#define PW    7
#define NBIN  (PH*PW)          // 49
#define PLANE (FH*FW)          // 36864
#define SMEM_PITCH 257         // odd pitch -> conflict-free column reads
#define MAXBIN 25              // bins per block (split 25/24)

// NHWC fp16 copy of the feature map: (B, H, W, C) = 37.7 MB
__device__ __half g_nhwc[BATCH * FH * FW * C_CH];

// ---------------------------------------------------------------------------
// Kernel 1: NCHW fp32 -> NHWC fp16 transpose (unchanged; near DRAM limit)
// ---------------------------------------------------------------------------
__global__ __launch_bounds__(256)
void transpose_kernel(const float* __restrict__ in)
{
    __shared__ __half tile[32][66];
    int pTile = blockIdx.x * 32;
    int cTile = blockIdx.y * 64;
    int b     = blockIdx.z;
    int tx = threadIdx.x;
    int ty = threadIdx.y;

    const float* src = in + (size_t)b * C_CH * PLANE;

    #pragma unroll
    for (int j = 0; j < 8; j++) {
        int cl = ty + 8 * j;
        int c  = cTile + cl;
        tile[tx][cl] = __float2half(src[(size_t)c * PLANE + pTile + tx]);
    }
    __syncthreads();

    __half2* dst = (__half2*)(g_nhwc + (size_t)b * PLANE * C_CH);
    #pragma unroll
    for (int j = 0; j < 4; j++) {
        int pl = ty + 8 * j;
        int p  = pTile + pl;
        __half2 h = ((const __half2*)&tile[pl][0])[tx];
        dst[(size_t)p * (C_CH / 2) + (cTile / 2) + tx] = h;
    }
}

// ---------------------------------------------------------------------------
// Kernel 2: one block handles CNT bins of one roi.
// Lanes: cg = tid&31 -> 8 fp16 channels via uint4 LDG.128.
// Pipeline: 2-sample double buffer (MLP 8). Math: fp16 HFMA2 partials,
// fp32 accumulate per sample.
// Staging smem layout is CHANNEL-INTERLEAVED: channel c of bin sl lives at
// word sl*257 + (c&7)*32 + (c>>3). Phase B stores (lanes=cg, stride 1) and
// Phase C column reads (lanes=sl, stride 257 === 1 mod 32) are BOTH
// bank-conflict-free.
// ---------------------------------------------------------------------------
__device__ __forceinline__ void load_taps(const uint4* __restrict__ fp,
                                          int4 off, int cg, uint4 q[4])
{
    q[0] = __ldg(fp + off.x + cg);
    q[1] = __ldg(fp + off.y + cg);
    q[2] = __ldg(fp + off.z + cg);
    q[3] = __ldg(fp + off.w + cg);
}

__device__ __forceinline__ void acc_sample(const uint4 q[4], uint4 wq,
                                           float a[8])
{
    __half2 p0 = __float2half2_rn(0.f);
    __half2 p1 = p0, p2 = p0, p3 = p0;

    #pragma unroll
    for (int k = 0; k < 4; k++) {
        unsigned int wu = (k == 0) ? wq.x : (k == 1) ? wq.y
                        : (k == 2) ? wq.z : wq.w;
        __half2 w2 = *(__half2*)&wu;
        const __half2* h = (const __half2*)&q[k];
        p0 = __hfma2(h[0], w2, p0);
        p1 = __hfma2(h[1], w2, p1);
        p2 = __hfma2(h[2], w2, p2);
        p3 = __hfma2(h[3], w2, p3);
    }

    float2 f0 = __half22float2(p0);
    float2 f1 = __half22float2(p1);
    float2 f2 = __half22float2(p2);
    float2 f3 = __half22float2(p3);
    a[0] += f0.x; a[1] += f0.y; a[2] += f1.x; a[3] += f1.y;
    a[4] += f2.x; a[5] += f2.y; a[6] += f3.x; a[7] += f3.y;
}

template<int S0, int CNT>
__device__ __forceinline__
void roi_body(float* sacc, int4* goff, uint4* gwh,
              const float* __restrict__ rois,
              const void*  __restrict__ stride_ptr,
              float* __restrict__ out)
{
    int n   = blockIdx.x;
    int tid = threadIdx.x;
    int cg  = tid & 31;        // channel group: channels 8cg..8cg+7
    int sg  = tid >> 5;        // bin subset 0..7

    const float* r = rois + n * 5;
    int b = (int)r[0];

    // ---- Phase A: geometry precompute (one thread per sample) ----
    if (tid < CNT * 4) {
        int iv = *(const int*)stride_ptr;
        float stride_f = (iv > 0 && iv < 65536) ? (float)iv
                                                : *(const float*)stride_ptr;
        float scale = 1.0f / stride_f;

        float x1 = r[1] * scale;
        float y1 = r[2] * scale;
        float x2 = r[3] * scale;
        float y2 = r[4] * scale;
        float bin_w = fmaxf(x2 - x1, 1.0f) * (1.0f / PW);
        float bin_h = fmaxf(y2 - y1, 1.0f) * (1.0f / PH);

        int s  = S0 + (tid >> 2);
        int j  = tid & 3;
        int iy = j >> 1;
        int ix = j & 1;
        int ph = s / PW;
        int pw = s - ph * PW;

        float yy = y1 + ((float)(ph * 2 + iy) + 0.5f) * 0.5f * bin_h;
        float xx = x1 + ((float)(pw * 2 + ix) + 0.5f) * 0.5f * bin_w;
        bool vy = (yy > -1.0f) && (yy < (float)FH);
        bool vx = (xx > -1.0f) && (xx < (float)FW);

        float cy = fminf(fmaxf(yy, 0.0f), (float)(FH - 1));
        float cx = fminf(fmaxf(xx, 0.0f), (float)(FW - 1));
        int y0 = min((int)floorf(cy), FH - 1);
        int x0 = min((int)floorf(cx), FW - 1);
        int y1r = min(y0 + 1, FH - 1);
        int x1r = min(x0 + 1, FW - 1);
        float fy = cy - (float)y0;
        float fx = cx - (float)x0;
        float hy = 1.0f - fy;
        float hx = 1.0f - fx;

        // fold mask and the 1/4 mean into fp16-duplicated weights
        float m = (vy && vx) ? 0.25f : 0.0f;
        __half2 w00 = __float2half2_rn(m * hy * hx);
        __half2 w01 = __float2half2_rn(m * hy * fx);
        __half2 w10 = __float2half2_rn(m * fy * hx);
        __half2 w11 = __float2half2_rn(m * fy * fx);
        uint4 wq;
        wq.x = *(unsigned int*)&w00;
        wq.y = *(unsigned int*)&w01;
        wq.z = *(unsigned int*)&w10;
        wq.w = *(unsigned int*)&w11;
        gwh[tid]  = wq;
        goff[tid] = make_int4((y0  * FW + x0 ) * (C_CH/8),
                              (y0  * FW + x1r) * (C_CH/8),
                              (y1r * FW + x0 ) * (C_CH/8),
                              (y1r * FW + x1r) * (C_CH/8));
    }
    __syncthreads();

    // ---- Phase B: accumulate, 2-sample pipelined loads (MLP 8) ----
    const uint4* fp = (const uint4*)(g_nhwc) + (size_t)b * PLANE * (C_CH / 8);

    for (int sl = sg; sl < CNT; sl += 8) {
        float a[8] = {0.f, 0.f, 0.f, 0.f, 0.f, 0.f, 0.f, 0.f};

        uint4 qa[4], qb[4];
        load_taps(fp, goff[sl*4+0], cg, qa);   // sample 0 in flight
        load_taps(fp, goff[sl*4+1], cg, qb);   // sample 1 in flight (MLP 8)
        acc_sample(qa, gwh[sl*4+0], a);
        load_taps(fp, goff[sl*4+2], cg, qa);   // sample 2 in flight
        acc_sample(qb, gwh[sl*4+1], a);
        load_taps(fp, goff[sl*4+3], cg, qb);   // sample 3 in flight
        acc_sample(qa, gwh[sl*4+2], a);
        acc_sample(qb, gwh[sl*4+3], a);

        // channel-interleaved store: c = 8*cg + k  ->  word k*32 + cg
        float* sp = &sacc[sl * SMEM_PITCH + cg];
        #pragma unroll
        for (int k = 0; k < 8; k++)
            sp[k * 32] = a[k];                 // STS.32, lanes stride 1: no conflict
    }

    __syncthreads();

    // ---- Phase C: coalesced writeout out[n][c][S0+sl] ----
    // read: word sl*257 + (c&7)*32 + (c>>3); lane stride 257 === 1 mod 32
    float* obase = out + (size_t)n * (C_CH * NBIN) + S0;
    for (int t = tid; t < C_CH * CNT; t += 256) {
        int c  = t / CNT;          // constexpr CNT -> magic multiply
        int sl = t - c * CNT;
        obase[c * NBIN + sl] = sacc[sl * SMEM_PITCH + (c & 7) * 32 + (c >> 3)];
    }
}

__global__ __launch_bounds__(256, 5)
void roi_align_nhwc_kernel(const float* __restrict__ rois,
                           const void*  __restrict__ stride_ptr,
                           float* __restrict__ out)
{
    __shared__ float sacc[MAXBIN * SMEM_PITCH];  // ~25.7 KB
    __shared__ int4  goff[MAXBIN * 4];           // 1.6 KB
    __shared__ uint4 gwh[MAXBIN * 4];            // 1.6 KB

    if (blockIdx.y == 0)
        roi_body<0, 25>(sacc, goff, gwh, rois, stride_ptr, out);
    else
        roi_body<25, 24>(sacc, goff, gwh, rois, stride_ptr, out);
}

extern "C" void kernel_launch(void* const* d_in, const int* in_sizes, int n_in,
                              void* d_out, int out_size)
{
    const float* rois    = (const float*)d_in[0];
    const float* feature = (const float*)d_in[1];
    const void*  stridep = d_in[2];
    float* out = (float*)d_out;

    int N = in_sizes[0] / 5;

    dim3 tgrid(PLANE / 32, C_CH / 64, BATCH);
    dim3 tblk(32, 8);
    transpose_kernel<<<tgrid, tblk>>>(feature);

    dim3 rgrid(N, 2);
    roi_align_nhwc_kernel<<<rgrid, 256>>>(rois, stridep, out);
}